// round 14
// baseline (speedup 1.0000x reference)
#include <cuda_runtime.h>
#include <cuda_bf16.h>
#include <math.h>
#include <stdint.h>

#define BB   64
#define DD   4096
#define HH   32
#define HDIM 128
#define PBS  16
#define MBSN 32
#define DFF  16384
#define NSLAB 4

// ---------------- device scratch ----------------
__device__ float g_q  [BB * DD];
__device__ float g_k  [BB * DD];
__device__ float g_v  [BB * DD];
__device__ float g_x2 [BB * DD];
__device__ float g_pt [16][BB * DD];     // split-K partials / attention partials
__device__ float g_ff1 [BB * DFF];
__device__ float g_ff1b[BB * DFF];
__device__ float g_ff3 [BB * DFF];
__device__ float g_ff3b[BB * DFF];
// pre-split bf16 activations (hi/lo)
__device__ __nv_bfloat16 g_hh [BB * DD],  g_hl [BB * DD];
__device__ __nv_bfloat16 g_ath[BB * DD],  g_atl[BB * DD];
__device__ __nv_bfloat16 g_h2h[BB * DD],  g_h2l[BB * DD];
__device__ __nv_bfloat16 g_gh [BB * DFF], g_gl [BB * DFF];

// ---------------- PTX helpers ----------------
#define LDSM4(r0, r1, r2, r3, addr)                                          \
    asm volatile("ldmatrix.sync.aligned.m8n8.x4.shared.b16 {%0,%1,%2,%3}, [%4];" \
                 : "=r"(r0), "=r"(r1), "=r"(r2), "=r"(r3) : "r"(addr))

#define MMA16816(d, a0, a1, a2, a3, b0, b1)                                   \
    asm volatile("mma.sync.aligned.m16n8k16.row.col.f32.bf16.bf16.f32 "       \
                 "{%0,%1,%2,%3},{%4,%5,%6,%7},{%8,%9},{%0,%1,%2,%3};"         \
                 : "+f"(d[0]), "+f"(d[1]), "+f"(d[2]), "+f"(d[3])             \
                 : "r"(a0), "r"(a1), "r"(a2), "r"(a3), "r"(b0), "r"(b1))

#define CPASYNC16(sm, gp)                                                     \
    asm volatile("cp.async.cg.shared.global [%0], [%1], 16;"                  \
                 :: "r"(sm), "l"(gp) : "memory")
#define CPASYNC_COMMIT() asm volatile("cp.async.commit_group;" ::: "memory")
#define CPASYNC_WAIT0()  asm volatile("cp.async.wait_group 0;" ::: "memory")

// split fp32 -> (hi, lo) bf16, packed pairs
__device__ __forceinline__ void cvt_split4(float4 v, uint2& uh, uint2& ul)
{
    __nv_bfloat162 h01 = __floats2bfloat162_rn(v.x, v.y);
    __nv_bfloat162 h23 = __floats2bfloat162_rn(v.z, v.w);
    float lx = v.x - __bfloat162float(__low2bfloat16(h01));
    float ly = v.y - __bfloat162float(__high2bfloat16(h01));
    float lz = v.z - __bfloat162float(__low2bfloat16(h23));
    float lw = v.w - __bfloat162float(__high2bfloat16(h23));
    __nv_bfloat162 l01 = __floats2bfloat162_rn(lx, ly);
    __nv_bfloat162 l23 = __floats2bfloat162_rn(lz, lw);
    uh.x = *(unsigned int*)&h01; uh.y = *(unsigned int*)&h23;
    ul.x = *(unsigned int*)&l01; ul.y = *(unsigned int*)&l23;
}

// ---------------- bf16-split tensor-core GEMM (2-stage pipelined) --------
// A supplied pre-split (bf16 hi/lo) via cp.async; W batched-register-converted.
struct Job { const float* W; float* C; int k0, k1; };
struct GP  {
    const __nv_bfloat16* Ah;
    const __nv_bfloat16* Al;
    int lda; int ldc; int nbpj; Job jobs[16];
};

#define KPAD 72
#define ST_ELE (2 * 64 * KPAD + 2 * 128 * KPAD)
#define STAGE_BYTES (ST_ELE * 2)
#define A_LO_B (64 * KPAD * 2)

__global__ __launch_bounds__(256, 2) void bf16gemm_kernel(GP p)
{
    int job = blockIdx.x / p.nbpj;
    int nb  = blockIdx.x % p.nbpj;
    const float* W = p.jobs[job].W;
    float*       C = p.jobs[job].C;
    const int k0j = p.jobs[job].k0, k1j = p.jobs[job].k1;
    const int n0  = nb * 128;

    extern __shared__ __nv_bfloat16 smem_bf[];
    const unsigned int smem_u = (unsigned int)__cvta_generic_to_shared(smem_bf);

    const int tid = threadIdx.x, lane = tid & 31, w = tid >> 5;
    const int wm = w & 1, wn = w >> 1;

    const int arow = (lane & 7) + (lane & 8);
    const int acol = (lane & 16) >> 1;
    const int brow = (lane & 7) + ((lane & 16) >> 1);
    const int bcol = lane & 8;

    float acc[2][4][4];
#pragma unroll
    for (int i = 0; i < 2; i++)
#pragma unroll
        for (int j = 0; j < 4; j++)
#pragma unroll
            for (int t = 0; t < 4; t++) acc[i][j][t] = 0.f;

    // A cp.async indexing: row = tid>>3 (+32), 16B slot = tid&7
    const int car = tid >> 3;
    const int cas = tid & 7;
    const __nv_bfloat16* Ah0 = p.Ah + (size_t)car * p.lda + k0j + cas * 8;
    const __nv_bfloat16* Al0 = p.Al + (size_t)car * p.lda + k0j + cas * 8;
    const size_t arow32 = (size_t)32 * p.lda;
    const unsigned int ua0  = (unsigned int)(car * KPAD + cas * 8) * 2;
    const unsigned int ua32 = ua0 + 32 * KPAD * 2;

    // W loader indexing (batched rw[8] path, as R11/R13)
    const int lrowW = tid >> 1, lcolW = (tid & 1) * 32;
    const float* Wrow = W + (size_t)(n0 + lrowW) * p.lda + k0j + lcolW;
    __nv_bfloat16* sb_h0 = smem_bf + 2 * 64 * KPAD + lrowW * KPAD + lcolW;
    __nv_bfloat16* sb_l0 = sb_h0 + 128 * KPAD;

    unsigned int a_base[2], b_base[2];
#pragma unroll
    for (int mi = 0; mi < 2; mi++)
        a_base[mi] = (unsigned int)__cvta_generic_to_shared(
            smem_bf + (wm * 32 + mi * 16 + arow) * KPAD + acol);
#pragma unroll
    for (int nj = 0; nj < 2; nj++)
        b_base[nj] = (unsigned int)__cvta_generic_to_shared(
            smem_bf + 2 * 64 * KPAD + (wn * 32 + nj * 16 + brow) * KPAD + bcol);
    const unsigned int A_LO = A_LO_B;
    const unsigned int B_LO = 128 * KPAD * 2;

    const int nch = (k1j - k0j) >> 6;

    // ---- prologue: chunk 0 ----
    {
        CPASYNC16(smem_u + ua0,         Ah0);
        CPASYNC16(smem_u + ua32,        Ah0 + arow32);
        CPASYNC16(smem_u + ua0 + A_LO,  Al0);
        CPASYNC16(smem_u + ua32 + A_LO, Al0 + arow32);
        CPASYNC_COMMIT();
        float4 rw[8];
#pragma unroll
        for (int i = 0; i < 8; i++) rw[i] = *(const float4*)(Wrow + 4 * i);
#pragma unroll
        for (int i = 0; i < 8; i++) {
            uint2 uh, ul;
            cvt_split4(rw[i], uh, ul);
            *(uint2*)(sb_h0 + 4 * i) = uh;
            *(uint2*)(sb_l0 + 4 * i) = ul;
        }
        CPASYNC_WAIT0();
        __syncthreads();
    }

    for (int c = 0; c < nch; c++) {
        const bool more = (c + 1) < nch;
        const int kn = (c + 1) * 64;
        const unsigned int stb = (unsigned int)((c + 1) & 1) * STAGE_BYTES;
        const int st = ((c + 1) & 1) * ST_ELE;

        float4 rw[8];
        if (more) {
            // A next chunk via cp.async (no registers held)
            CPASYNC16(smem_u + stb + ua0,         Ah0 + kn);
            CPASYNC16(smem_u + stb + ua32,        Ah0 + kn + arow32);
            CPASYNC16(smem_u + stb + ua0 + A_LO,  Al0 + kn);
            CPASYNC16(smem_u + stb + ua32 + A_LO, Al0 + kn + arow32);
            CPASYNC_COMMIT();
            // W next chunk, batched LDGs at chunk top
#pragma unroll
            for (int i = 0; i < 8; i++) rw[i] = *(const float4*)(Wrow + kn + 4 * i);
        }

        const unsigned int sb_off = (unsigned int)(c & 1) * STAGE_BYTES;
#pragma unroll
        for (int ks = 0; ks < 4; ks++) {
            const unsigned int koff = sb_off + ks * 16 * 2;
            unsigned int ah[2][4], al[2][4], bh[2][4], bl[2][4];
#pragma unroll
            for (int mi = 0; mi < 2; mi++) {
                LDSM4(ah[mi][0], ah[mi][1], ah[mi][2], ah[mi][3], a_base[mi] + koff);
                LDSM4(al[mi][0], al[mi][1], al[mi][2], al[mi][3], a_base[mi] + koff + A_LO);
            }
#pragma unroll
            for (int nj = 0; nj < 2; nj++) {
                LDSM4(bh[nj][0], bh[nj][1], bh[nj][2], bh[nj][3], b_base[nj] + koff);
                LDSM4(bl[nj][0], bl[nj][1], bl[nj][2], bl[nj][3], b_base[nj] + koff + B_LO);
            }
#pragma unroll
            for (int mi = 0; mi < 2; mi++)
#pragma unroll
                for (int ni = 0; ni < 4; ni++) {
                    const int nj = ni >> 1, of = (ni & 1) * 2;
                    MMA16816(acc[mi][ni], ah[mi][0], ah[mi][1], ah[mi][2], ah[mi][3],
                             bh[nj][of], bh[nj][of + 1]);
                    MMA16816(acc[mi][ni], ah[mi][0], ah[mi][1], ah[mi][2], ah[mi][3],
                             bl[nj][of], bl[nj][of + 1]);
                    MMA16816(acc[mi][ni], al[mi][0], al[mi][1], al[mi][2], al[mi][3],
                             bh[nj][of], bh[nj][of + 1]);
                }
        }

        if (more) {
#pragma unroll
            for (int i = 0; i < 8; i++) {
                uint2 uh, ul;
                cvt_split4(rw[i], uh, ul);
                *(uint2*)(sb_h0 + st + 4 * i) = uh;
                *(uint2*)(sb_l0 + st + 4 * i) = ul;
            }
        }
        CPASYNC_WAIT0();
        __syncthreads();
    }

    const int tr = lane >> 2, tc = (lane & 3) * 2;
#pragma unroll
    for (int mi = 0; mi < 2; mi++) {
        const int m = wm * 32 + mi * 16 + tr;
#pragma unroll
        for (int ni = 0; ni < 4; ni++) {
            const int n = n0 + wn * 32 + ni * 8 + tc;
            float2 r0 = {acc[mi][ni][0], acc[mi][ni][1]};
            float2 r1 = {acc[mi][ni][2], acc[mi][ni][3]};
            *(float2*)&C[(size_t)m * p.ldc + n]       = r0;
            *(float2*)&C[(size_t)(m + 8) * p.ldc + n] = r1;
        }
    }
}

// ---------------- RMSNorm -> bf16 hi/lo ----------------
__global__ __launch_bounds__(256) void rmsnorm_kernel(
    const float* __restrict__ x, const float* __restrict__ g,
    __nv_bfloat16* __restrict__ oh, __nv_bfloat16* __restrict__ ol)
{
    int row = blockIdx.x, tid = threadIdx.x;
    const float4* xr = (const float4*)(x + (size_t)row * DD);
    const float4* gr = (const float4*)g;
    float4 v[4];
    float ss = 0.f;
#pragma unroll
    for (int i = 0; i < 4; i++) {
        v[i] = xr[tid + 256 * i];
        ss += v[i].x * v[i].x + v[i].y * v[i].y + v[i].z * v[i].z + v[i].w * v[i].w;
    }
#pragma unroll
    for (int o = 16; o; o >>= 1) ss += __shfl_xor_sync(0xffffffffu, ss, o);
    __shared__ float sred[8];
    if ((tid & 31) == 0) sred[tid >> 5] = ss;
    __syncthreads();
    float tot = 0.f;
#pragma unroll
    for (int i = 0; i < 8; i++) tot += sred[i];
    float inv = rsqrtf(tot / (float)DD + 1e-5f);
#pragma unroll
    for (int i = 0; i < 4; i++) {
        int idx = tid + 256 * i;
        float4 gv = gr[idx];
        float4 o4;
        o4.x = v[i].x * inv * gv.x;
        o4.y = v[i].y * inv * gv.y;
        o4.z = v[i].z * inv * gv.z;
        o4.w = v[i].w * inv * gv.w;
        uint2 uh, ul;
        cvt_split4(o4, uh, ul);
        *(uint2*)(oh + (size_t)row * DD + idx * 4) = uh;
        *(uint2*)(ol + (size_t)row * DD + idx * 4) = ul;
    }
}

// ---------------- combine QKV split-K partials ----------------
__global__ __launch_bounds__(256) void qkv_combine_kernel()
{
    int idx = blockIdx.x * 256 + threadIdx.x;
#pragma unroll
    for (int m = 0; m < 3; m++) {
        float4 s = ((const float4*)g_pt[m * 4 + 0])[idx];
#pragma unroll
        for (int j = 1; j < 4; j++) {
            float4 t = ((const float4*)g_pt[m * 4 + j])[idx];
            s.x += t.x; s.y += t.y; s.z += t.z; s.w += t.w;
        }
        float* dst = (m == 0) ? g_q : (m == 1) ? g_k : g_v;
        ((float4*)dst)[idx] = s;
    }
}

// ---------------- flash-decode attention: slab partial (R10 variant) ------
__global__ __launch_bounds__(256) void attn_partial_kernel(
    const float* __restrict__ kheap, const float* __restrict__ vheap,
    const int*   __restrict__ btab,  const int*  __restrict__ clens,
    const float* __restrict__ scale_p)
{
    const int hh = blockIdx.x, b = blockIdx.y, slab = blockIdx.z;
    const int ctx = clens[b];
    const int base = slab * 128;
    if (base >= ctx) return;
    const int send = min(ctx, base + 128);

    const int tid = threadIdx.x, lane = tid & 31, w = tid >> 5;
    const float scale = scale_p[0];
    const int last = ctx - 1;

    const float4 qv = ((const float4*)(g_q + (size_t)b * DD + hh * HDIM))[lane];

    float m = -1e30f, l = 0.f;
    float4 acc = {0.f, 0.f, 0.f, 0.f};

    for (int s = base + w; s < send; s += 8) {
        const float *kp, *vp;
        if (s == last) {
            kp = g_k + (size_t)b * DD + hh * HDIM;
            vp = g_v + (size_t)b * DD + hh * HDIM;
        } else {
            int blk = btab[b * MBSN + (s >> 4)];
            size_t hbase = (((size_t)blk * HH + hh) * PBS + (s & 15)) * HDIM;
            kp = kheap + hbase;
            vp = vheap + hbase;
        }
        float4 kv = *(const float4*)(kp + lane * 4);
        float4 vv = *(const float4*)(vp + lane * 4);
        float sc = qv.x * kv.x + qv.y * kv.y + qv.z * kv.z + qv.w * kv.w;
#pragma unroll
        for (int o = 16; o; o >>= 1) sc += __shfl_xor_sync(0xffffffffu, sc, o);
        sc *= scale;
        float mn   = fmaxf(m, sc);
        float corr = expf(m - mn);
        float pw   = expf(sc - mn);
        l = l * corr + pw;
        acc.x = fmaf(pw, vv.x, acc.x * corr);
        acc.y = fmaf(pw, vv.y, acc.y * corr);
        acc.z = fmaf(pw, vv.z, acc.z * corr);
        acc.w = fmaf(pw, vv.w, acc.w * corr);
        m = mn;
    }

    __shared__ float sm_m[8], sm_l[8];
    __shared__ float sm_acc[8][HDIM];
    if (lane == 0) { sm_m[w] = m; sm_l[w] = l; }
    ((float4*)sm_acc[w])[lane] = acc;
    __syncthreads();

    if (tid < HDIM) {
        const int d = tid;
        float M = -1e30f;
#pragma unroll
        for (int i = 0; i < 8; i++) M = fmaxf(M, sm_m[i]);
        float L = 0.f, O = 0.f;
#pragma unroll
        for (int i = 0; i < 8; i++) {
            float e = expf(sm_m[i] - M);
            L += sm_l[i] * e;
            O += sm_acc[i][d] * e;
        }
        const int bh = b * HH + hh;
        if (d == 0) {
            g_pt[0][slab * 2048 + bh]        = M;
            g_pt[0][8192 + slab * 2048 + bh] = L;
        }
        g_pt[4 + slab][(size_t)bh * HDIM + d] = O;
    }
}

// ---------------- flash-decode attention: slab reduce -> att bf16 hi/lo ----
__global__ __launch_bounds__(128) void attn_reduce_kernel(const int* __restrict__ clens)
{
    const int hh = blockIdx.x, b = blockIdx.y, d = threadIdx.x;
    const int ctx = clens[b];
    const int ns = (ctx + 127) >> 7;
    const int bh = b * HH + hh;

    float M = -1e30f;
    for (int s = 0; s < ns; s++) M = fmaxf(M, g_pt[0][s * 2048 + bh]);
    float L = 0.f, O = 0.f;
    for (int s = 0; s < ns; s++) {
        float e = expf(g_pt[0][s * 2048 + bh] - M);
        L += g_pt[0][8192 + s * 2048 + bh] * e;
        O += g_pt[4 + s][(size_t)bh * HDIM + d] * e;
    }
    float o = O / L;
    __nv_bfloat16 hi = __float2bfloat16_rn(o);
    __nv_bfloat16 lo = __float2bfloat16_rn(o - __bfloat162float(hi));
    g_ath[(size_t)b * DD + hh * HDIM + d] = hi;
    g_atl[(size_t)b * DD + hh * HDIM + d] = lo;
}

// ---------------- x2 = sum(pt)+resid ; h2 = rmsnorm(x2)*g -> bf16 hi/lo ----
__global__ __launch_bounds__(256) void addreduce_rms_kernel(
    const float* __restrict__ resid, const float* __restrict__ g,
    float* __restrict__ xout)
{
    int row = blockIdx.x, tid = threadIdx.x;
    const float4* r4 = (const float4*)(resid + (size_t)row * DD);
    const float4* gr = (const float4*)g;
    float4 v[4];
    float ss = 0.f;
#pragma unroll
    for (int i = 0; i < 4; i++) {
        int idx = tid + 256 * i;
        float4 s = r4[idx];
#pragma unroll
        for (int j = 0; j < 16; j++) {
            float4 t = ((const float4*)(g_pt[j] + (size_t)row * DD))[idx];
            s.x += t.x; s.y += t.y; s.z += t.z; s.w += t.w;
        }
        v[i] = s;
        ss += s.x * s.x + s.y * s.y + s.z * s.z + s.w * s.w;
    }
#pragma unroll
    for (int o = 16; o; o >>= 1) ss += __shfl_xor_sync(0xffffffffu, ss, o);
    __shared__ float sred[8];
    if ((tid & 31) == 0) sred[tid >> 5] = ss;
    __syncthreads();
    float tot = 0.f;
#pragma unroll
    for (int i = 0; i < 8; i++) tot += sred[i];
    float inv = rsqrtf(tot / (float)DD + 1e-5f);
    float4* xo = (float4*)(xout + (size_t)row * DD);
#pragma unroll
    for (int i = 0; i < 4; i++) {
        int idx = tid + 256 * i;
        xo[idx] = v[i];
        float4 gv = gr[idx];
        float4 o4;
        o4.x = v[i].x * inv * gv.x;
        o4.y = v[i].y * inv * gv.y;
        o4.z = v[i].z * inv * gv.z;
        o4.w = v[i].w * inv * gv.w;
        uint2 uh, ul;
        cvt_split4(o4, uh, ul);
        *(uint2*)(g_h2h + (size_t)row * DD + idx * 4) = uh;
        *(uint2*)(g_h2l + (size_t)row * DD + idx * 4) = ul;
    }
}

// ---------------- gate = silu(ff1a+ff1b)*(ff3a+ff3b) -> bf16 hi/lo ---------
__global__ __launch_bounds__(256) void silu_mul_kernel()
{
    int idx = blockIdx.x * 256 + threadIdx.x;
    float4 a  = ((const float4*)g_ff1)[idx];
    float4 ab = ((const float4*)g_ff1b)[idx];
    float4 c  = ((const float4*)g_ff3)[idx];
    float4 cb = ((const float4*)g_ff3b)[idx];
    a.x += ab.x; a.y += ab.y; a.z += ab.z; a.w += ab.w;
    c.x += cb.x; c.y += cb.y; c.z += cb.z; c.w += cb.w;
    float4 o;
    o.x = a.x / (1.f + __expf(-a.x)) * c.x;
    o.y = a.y / (1.f + __expf(-a.y)) * c.y;
    o.z = a.z / (1.f + __expf(-a.z)) * c.z;
    o.w = a.w / (1.f + __expf(-a.w)) * c.w;
    uint2 uh, ul;
    cvt_split4(o, uh, ul);
    *(uint2*)(g_gh + (size_t)idx * 4) = uh;
    *(uint2*)(g_gl + (size_t)idx * 4) = ul;
}

// ---------------- out = sum(pt) + resid ----------------
__global__ __launch_bounds__(256) void final_add_kernel(
    const float* __restrict__ resid, float* __restrict__ out)
{
    int idx = blockIdx.x * 256 + threadIdx.x;
    float4 s = ((const float4*)resid)[idx];
#pragma unroll
    for (int j = 0; j < 16; j++) {
        float4 t = ((const float4*)g_pt[j])[idx];
        s.x += t.x; s.y += t.y; s.z += t.z; s.w += t.w;
    }
    ((float4*)out)[idx] = s;
}

// ---------------- host driver ----------------
extern "C" void kernel_launch(void* const* d_in, const int* in_sizes, int n_in,
                              void* d_out, int out_size)
{
    const float* x     = (const float*)d_in[0];
    const float* kheap = (const float*)d_in[1];
    const float* vheap = (const float*)d_in[2];
    const int*   btab  = (const int*)d_in[3];
    const int*   clens = (const int*)d_in[5];
    const float* scale = (const float*)d_in[9];
    const float* Wq    = (const float*)d_in[13];
    const float* Wk    = (const float*)d_in[14];
    const float* Wv    = (const float*)d_in[15];
    const float* Wo    = (const float*)d_in[16];
    const float* W1    = (const float*)d_in[17];
    const float* W2    = (const float*)d_in[18];
    const float* W3    = (const float*)d_in[19];
    const float* g1    = (const float*)d_in[20];
    const float* g2    = (const float*)d_in[21];
    float* out = (float*)d_out;

    float *x2, *ff1, *ff1b, *ff3, *ff3b;
    __nv_bfloat16 *hh, *hl, *ath, *atl, *h2h, *h2l, *gh, *gl;
    float* pt[16];
    cudaGetSymbolAddress((void**)&x2,   g_x2);
    cudaGetSymbolAddress((void**)&ff1,  g_ff1);
    cudaGetSymbolAddress((void**)&ff1b, g_ff1b);
    cudaGetSymbolAddress((void**)&ff3,  g_ff3);
    cudaGetSymbolAddress((void**)&ff3b, g_ff3b);
    cudaGetSymbolAddress((void**)&hh,   g_hh);
    cudaGetSymbolAddress((void**)&hl,   g_hl);
    cudaGetSymbolAddress((void**)&ath,  g_ath);
    cudaGetSymbolAddress((void**)&atl,  g_atl);
    cudaGetSymbolAddress((void**)&h2h,  g_h2h);
    cudaGetSymbolAddress((void**)&h2l,  g_h2l);
    cudaGetSymbolAddress((void**)&gh,   g_gh);
    cudaGetSymbolAddress((void**)&gl,   g_gl);
    {
        float* base;
        cudaGetSymbolAddress((void**)&base, g_pt);
        for (int j = 0; j < 16; j++) pt[j] = base + (size_t)j * BB * DD;
    }

    const int SMEM = 2 * STAGE_BYTES;
    cudaFuncSetAttribute(bf16gemm_kernel,
                         cudaFuncAttributeMaxDynamicSharedMemorySize, SMEM);

    // 1) h = rmsnorm(x)*g1 -> bf16 hi/lo
    rmsnorm_kernel<<<BB, 256>>>(x, g1, hh, hl);

    // 2) q,k,v = h @ {Wq,Wk,Wv}^T   split-K=4 each -> 384 CTAs
    {
        GP p;
        p.Ah = hh; p.Al = hl; p.lda = DD; p.ldc = DD; p.nbpj = DD / 128;
        const float* Ws[3] = {Wq, Wk, Wv};
        for (int m = 0; m < 3; m++)
            for (int s = 0; s < 4; s++)
                p.jobs[m * 4 + s] = {Ws[m], pt[m * 4 + s], s * (DD / 4), (s + 1) * (DD / 4)};
        bf16gemm_kernel<<<12 * (DD / 128), 256, SMEM>>>(p);
    }
    qkv_combine_kernel<<<(BB * DD) / 4 / 256, 256>>>();

    // 3) flash-decode attention
    attn_partial_kernel<<<dim3(HH, BB, NSLAB), 256>>>(kheap, vheap, btab, clens, scale);
    attn_reduce_kernel<<<dim3(HH, BB), 128>>>(clens);

    // 4) att @ Wo^T, split-K=16 -> 512 CTAs
    {
        GP p;
        p.Ah = ath; p.Al = atl; p.lda = DD; p.ldc = DD; p.nbpj = DD / 128;
        for (int s = 0; s < 16; s++)
            p.jobs[s] = {Wo, pt[s], s * (DD / 16), (s + 1) * (DD / 16)};
        bf16gemm_kernel<<<16 * (DD / 128), 256, SMEM>>>(p);
    }

    // 5) x2 = sum(pt)+x ; h2 -> bf16 hi/lo
    addreduce_rms_kernel<<<BB, 256>>>(x, g2, x2);

    // 6) ff1 = h2 @ W1^T, ff3 = h2 @ W3^T, split-K=2 each -> 512 CTAs
    {
        GP p;
        p.Ah = h2h; p.Al = h2l; p.lda = DD; p.ldc = DFF; p.nbpj = DFF / 128;
        p.jobs[0] = {W1, ff1,  0,      DD / 2};
        p.jobs[1] = {W1, ff1b, DD / 2, DD};
        p.jobs[2] = {W3, ff3,  0,      DD / 2};
        p.jobs[3] = {W3, ff3b, DD / 2, DD};
        bf16gemm_kernel<<<4 * (DFF / 128), 256, SMEM>>>(p);
    }

    // 7) gate -> bf16 hi/lo
    silu_mul_kernel<<<(BB * DFF) / 4 / 256, 256>>>();

    // 8) gate @ W2^T, split-K=16 -> 512 CTAs
    {
        GP p;
        p.Ah = gh; p.Al = gl; p.lda = DFF; p.ldc = DD; p.nbpj = DD / 128;
        for (int s = 0; s < 16; s++)
            p.jobs[s] = {W2, pt[s], s * (DFF / 16), (s + 1) * (DFF / 16)};
        bf16gemm_kernel<<<16 * (DD / 128), 256, SMEM>>>(p);
    }

    // 9) out = sum(pt) + x2
    final_add_kernel<<<(BB * DD) / 4 / 256, 256>>>(x2, out);
}

// round 15
// speedup vs baseline: 1.4309x; 1.4309x over previous
#include <cuda_runtime.h>
#include <cuda_bf16.h>
#include <math.h>
#include <stdint.h>

#define BB   64
#define DD   4096
#define HH   32
#define HDIM 128
#define PBS  16
#define MBSN 32
#define DFF  16384
#define NSLAB 4

// ---------------- device scratch ----------------
__device__ float g_q  [BB * DD];
__device__ float g_k  [BB * DD];
__device__ float g_v  [BB * DD];
__device__ float g_x2 [BB * DD];
__device__ float g_pt [16][BB * DD];     // split-K partials / attention partials
__device__ float g_ff1 [BB * DFF];
__device__ float g_ff1b[BB * DFF];
__device__ float g_ff3 [BB * DFF];
__device__ float g_ff3b[BB * DFF];
// pre-split bf16 activations (hi/lo)
__device__ __nv_bfloat16 g_hh [BB * DD],  g_hl [BB * DD];
__device__ __nv_bfloat16 g_ath[BB * DD],  g_atl[BB * DD];
__device__ __nv_bfloat16 g_h2h[BB * DD],  g_h2l[BB * DD];
__device__ __nv_bfloat16 g_gh [BB * DFF], g_gl [BB * DFF];

// ---------------- PTX helpers ----------------
#define LDSM4(r0, r1, r2, r3, addr)                                          \
    asm volatile("ldmatrix.sync.aligned.m8n8.x4.shared.b16 {%0,%1,%2,%3}, [%4];" \
                 : "=r"(r0), "=r"(r1), "=r"(r2), "=r"(r3) : "r"(addr))

#define MMA16816(d, a0, a1, a2, a3, b0, b1)                                   \
    asm volatile("mma.sync.aligned.m16n8k16.row.col.f32.bf16.bf16.f32 "       \
                 "{%0,%1,%2,%3},{%4,%5,%6,%7},{%8,%9},{%0,%1,%2,%3};"         \
                 : "+f"(d[0]), "+f"(d[1]), "+f"(d[2]), "+f"(d[3])             \
                 : "r"(a0), "r"(a1), "r"(a2), "r"(a3), "r"(b0), "r"(b1))

// split fp32 -> (hi, lo) bf16, packed pairs
__device__ __forceinline__ void cvt_split4(float4 v, uint2& uh, uint2& ul)
{
    __nv_bfloat162 h01 = __floats2bfloat162_rn(v.x, v.y);
    __nv_bfloat162 h23 = __floats2bfloat162_rn(v.z, v.w);
    float lx = v.x - __bfloat162float(__low2bfloat16(h01));
    float ly = v.y - __bfloat162float(__high2bfloat16(h01));
    float lz = v.z - __bfloat162float(__low2bfloat16(h23));
    float lw = v.w - __bfloat162float(__high2bfloat16(h23));
    __nv_bfloat162 l01 = __floats2bfloat162_rn(lx, ly);
    __nv_bfloat162 l23 = __floats2bfloat162_rn(lz, lw);
    uh.x = *(unsigned int*)&h01; uh.y = *(unsigned int*)&h23;
    ul.x = *(unsigned int*)&l01; ul.y = *(unsigned int*)&l23;
}

// ---------------- bf16-split tensor-core GEMM (2-stage pipelined) --------
// A pre-split (bf16 hi/lo). Loaders remapped for minimal L1tex wavefronts:
// every warp-LDG is lane-consecutive covering whole rows.
struct Job { const float* W; float* C; int k0, k1; };
struct GP  {
    const __nv_bfloat16* Ah;
    const __nv_bfloat16* Al;
    int lda; int ldc; int nbpj; Job jobs[16];
};

#define KPAD 72
#define ST_ELE (2 * 64 * KPAD + 2 * 128 * KPAD)
#define STAGE_BYTES (ST_ELE * 2)

__global__ __launch_bounds__(256, 2) void bf16gemm_kernel(GP p)
{
    int job = blockIdx.x / p.nbpj;
    int nb  = blockIdx.x % p.nbpj;
    const float* W = p.jobs[job].W;
    float*       C = p.jobs[job].C;
    const int k0j = p.jobs[job].k0, k1j = p.jobs[job].k1;
    const int n0  = nb * 128;

    extern __shared__ __nv_bfloat16 smem_bf[];

    const int tid = threadIdx.x, lane = tid & 31, w = tid >> 5;
    const int wm = w & 1, wn = w >> 1;

    const int arow = (lane & 7) + (lane & 8);
    const int acol = (lane & 16) >> 1;
    const int brow = (lane & 7) + ((lane & 16) >> 1);
    const int bcol = lane & 8;

    float acc[2][4][4];
#pragma unroll
    for (int i = 0; i < 2; i++)
#pragma unroll
        for (int j = 0; j < 4; j++)
#pragma unroll
            for (int t = 0; t < 4; t++) acc[i][j][t] = 0.f;

    // ---- A loader: warp covers 8 rows; each instr = 4 full rows ----
    // row = w*8 + j*4 + (lane>>3), col bf16 = (lane&7)*8
    const int aRow = (w << 3) + (lane >> 3);
    const int aCol = (lane & 7) * 8;
    const __nv_bfloat16* Ahp = p.Ah + (size_t)aRow * p.lda + k0j + aCol;
    const __nv_bfloat16* Alp = p.Al + (size_t)aRow * p.lda + k0j + aCol;
    const size_t aStep = (size_t)4 * p.lda;           // +4 rows
    __nv_bfloat16* saH = smem_bf + aRow * KPAD + aCol;

    // ---- W loader: warp covers 16 rows; each instr = 2 full rows ----
    // row = w*16 + i*2 + (lane>>4), col floats = (lane&15)*4
    const int wRow = (w << 4) + (lane >> 4);
    const int wCol = (lane & 15) * 4;
    const float* Wp = W + (size_t)(n0 + wRow) * p.lda + k0j + wCol;
    const size_t wStep = (size_t)2 * p.lda;           // +2 rows
    __nv_bfloat16* sbH = smem_bf + 2 * 64 * KPAD + wRow * KPAD + wCol;

    unsigned int a_base[2], b_base[2];
#pragma unroll
    for (int mi = 0; mi < 2; mi++)
        a_base[mi] = (unsigned int)__cvta_generic_to_shared(
            smem_bf + (wm * 32 + mi * 16 + arow) * KPAD + acol);
#pragma unroll
    for (int nj = 0; nj < 2; nj++)
        b_base[nj] = (unsigned int)__cvta_generic_to_shared(
            smem_bf + 2 * 64 * KPAD + (wn * 32 + nj * 16 + brow) * KPAD + bcol);
    const unsigned int A_LO = 64 * KPAD * 2;    // bytes
    const unsigned int B_LO = 128 * KPAD * 2;
    const int A_LOe = 64 * KPAD;                // elems
    const int B_LOe = 128 * KPAD;

    const int nch = (k1j - k0j) >> 6;

    uint4 rah[2], ral[2];
    float4 rw[8];
    rah[0] = *(const uint4*)(Ahp);          rah[1] = *(const uint4*)(Ahp + aStep);
    ral[0] = *(const uint4*)(Alp);          ral[1] = *(const uint4*)(Alp + aStep);
#pragma unroll
    for (int i = 0; i < 8; i++) rw[i] = *(const float4*)(Wp + (size_t)i * wStep);

    *(uint4*)(saH)                 = rah[0];
    *(uint4*)(saH + 4 * KPAD)      = rah[1];
    *(uint4*)(saH + A_LOe)             = ral[0];
    *(uint4*)(saH + A_LOe + 4 * KPAD)  = ral[1];
#pragma unroll
    for (int i = 0; i < 8; i++) {
        uint2 uh, ul;
        cvt_split4(rw[i], uh, ul);
        *(uint2*)(sbH + i * 2 * KPAD)          = uh;
        *(uint2*)(sbH + B_LOe + i * 2 * KPAD)  = ul;
    }
    __syncthreads();

    for (int c = 0; c < nch; c++) {
        const bool more = (c + 1) < nch;
        if (more) {
            const int kn = (c + 1) * 64;
            rah[0] = *(const uint4*)(Ahp + kn);          rah[1] = *(const uint4*)(Ahp + kn + aStep);
            ral[0] = *(const uint4*)(Alp + kn);          ral[1] = *(const uint4*)(Alp + kn + aStep);
#pragma unroll
            for (int i = 0; i < 8; i++) rw[i] = *(const float4*)(Wp + kn + (size_t)i * wStep);
        }

        const unsigned int sb_off = (unsigned int)(c & 1) * STAGE_BYTES;
#pragma unroll
        for (int ks = 0; ks < 4; ks++) {
            const unsigned int koff = sb_off + ks * 16 * 2;
            unsigned int ah[2][4], al[2][4], bh[2][4], bl[2][4];
#pragma unroll
            for (int mi = 0; mi < 2; mi++) {
                LDSM4(ah[mi][0], ah[mi][1], ah[mi][2], ah[mi][3], a_base[mi] + koff);
                LDSM4(al[mi][0], al[mi][1], al[mi][2], al[mi][3], a_base[mi] + koff + A_LO);
            }
#pragma unroll
            for (int nj = 0; nj < 2; nj++) {
                LDSM4(bh[nj][0], bh[nj][1], bh[nj][2], bh[nj][3], b_base[nj] + koff);
                LDSM4(bl[nj][0], bl[nj][1], bl[nj][2], bl[nj][3], b_base[nj] + koff + B_LO);
            }
#pragma unroll
            for (int mi = 0; mi < 2; mi++)
#pragma unroll
                for (int ni = 0; ni < 4; ni++) {
                    const int nj = ni >> 1, of = (ni & 1) * 2;
                    MMA16816(acc[mi][ni], ah[mi][0], ah[mi][1], ah[mi][2], ah[mi][3],
                             bh[nj][of], bh[nj][of + 1]);
                    MMA16816(acc[mi][ni], ah[mi][0], ah[mi][1], ah[mi][2], ah[mi][3],
                             bl[nj][of], bl[nj][of + 1]);
                    MMA16816(acc[mi][ni], al[mi][0], al[mi][1], al[mi][2], al[mi][3],
                             bh[nj][of], bh[nj][of + 1]);
                }
        }

        if (more) {
            const int st = ((c + 1) & 1) * ST_ELE;
            *(uint4*)(saH + st)                 = rah[0];
            *(uint4*)(saH + st + 4 * KPAD)      = rah[1];
            *(uint4*)(saH + st + A_LOe)             = ral[0];
            *(uint4*)(saH + st + A_LOe + 4 * KPAD)  = ral[1];
#pragma unroll
            for (int i = 0; i < 8; i++) {
                uint2 uh, ul;
                cvt_split4(rw[i], uh, ul);
                *(uint2*)(sbH + st + i * 2 * KPAD)          = uh;
                *(uint2*)(sbH + st + B_LOe + i * 2 * KPAD)  = ul;
            }
        }
        __syncthreads();
    }

    const int tr = lane >> 2, tc = (lane & 3) * 2;
#pragma unroll
    for (int mi = 0; mi < 2; mi++) {
        const int m = wm * 32 + mi * 16 + tr;
#pragma unroll
        for (int ni = 0; ni < 4; ni++) {
            const int n = n0 + wn * 32 + ni * 8 + tc;
            float2 r0 = {acc[mi][ni][0], acc[mi][ni][1]};
            float2 r1 = {acc[mi][ni][2], acc[mi][ni][3]};
            *(float2*)&C[(size_t)m * p.ldc + n]       = r0;
            *(float2*)&C[(size_t)(m + 8) * p.ldc + n] = r1;
        }
    }
}

// ---------------- RMSNorm -> bf16 hi/lo ----------------
__global__ __launch_bounds__(256) void rmsnorm_kernel(
    const float* __restrict__ x, const float* __restrict__ g,
    __nv_bfloat16* __restrict__ oh, __nv_bfloat16* __restrict__ ol)
{
    int row = blockIdx.x, tid = threadIdx.x;
    const float4* xr = (const float4*)(x + (size_t)row * DD);
    const float4* gr = (const float4*)g;
    float4 v[4];
    float ss = 0.f;
#pragma unroll
    for (int i = 0; i < 4; i++) {
        v[i] = xr[tid + 256 * i];
        ss += v[i].x * v[i].x + v[i].y * v[i].y + v[i].z * v[i].z + v[i].w * v[i].w;
    }
#pragma unroll
    for (int o = 16; o; o >>= 1) ss += __shfl_xor_sync(0xffffffffu, ss, o);
    __shared__ float sred[8];
    if ((tid & 31) == 0) sred[tid >> 5] = ss;
    __syncthreads();
    float tot = 0.f;
#pragma unroll
    for (int i = 0; i < 8; i++) tot += sred[i];
    float inv = rsqrtf(tot / (float)DD + 1e-5f);
#pragma unroll
    for (int i = 0; i < 4; i++) {
        int idx = tid + 256 * i;
        float4 gv = gr[idx];
        float4 o4;
        o4.x = v[i].x * inv * gv.x;
        o4.y = v[i].y * inv * gv.y;
        o4.z = v[i].z * inv * gv.z;
        o4.w = v[i].w * inv * gv.w;
        uint2 uh, ul;
        cvt_split4(o4, uh, ul);
        *(uint2*)(oh + (size_t)row * DD + idx * 4) = uh;
        *(uint2*)(ol + (size_t)row * DD + idx * 4) = ul;
    }
}

// ---------------- combine QKV split-K partials ----------------
__global__ __launch_bounds__(256) void qkv_combine_kernel()
{
    int idx = blockIdx.x * 256 + threadIdx.x;
#pragma unroll
    for (int m = 0; m < 3; m++) {
        float4 s = ((const float4*)g_pt[m * 4 + 0])[idx];
#pragma unroll
        for (int j = 1; j < 4; j++) {
            float4 t = ((const float4*)g_pt[m * 4 + j])[idx];
            s.x += t.x; s.y += t.y; s.z += t.z; s.w += t.w;
        }
        float* dst = (m == 0) ? g_q : (m == 1) ? g_k : g_v;
        ((float4*)dst)[idx] = s;
    }
}

// ---------------- flash-decode attention: slab partial (R10 variant) ------
__global__ __launch_bounds__(256) void attn_partial_kernel(
    const float* __restrict__ kheap, const float* __restrict__ vheap,
    const int*   __restrict__ btab,  const int*  __restrict__ clens,
    const float* __restrict__ scale_p)
{
    const int hh = blockIdx.x, b = blockIdx.y, slab = blockIdx.z;
    const int ctx = clens[b];
    const int base = slab * 128;
    if (base >= ctx) return;
    const int send = min(ctx, base + 128);

    const int tid = threadIdx.x, lane = tid & 31, w = tid >> 5;
    const float scale = scale_p[0];
    const int last = ctx - 1;

    const float4 qv = ((const float4*)(g_q + (size_t)b * DD + hh * HDIM))[lane];

    float m = -1e30f, l = 0.f;
    float4 acc = {0.f, 0.f, 0.f, 0.f};

    for (int s = base + w; s < send; s += 8) {
        const float *kp, *vp;
        if (s == last) {
            kp = g_k + (size_t)b * DD + hh * HDIM;
            vp = g_v + (size_t)b * DD + hh * HDIM;
        } else {
            int blk = btab[b * MBSN + (s >> 4)];
            size_t hbase = (((size_t)blk * HH + hh) * PBS + (s & 15)) * HDIM;
            kp = kheap + hbase;
            vp = vheap + hbase;
        }
        float4 kv = *(const float4*)(kp + lane * 4);
        float4 vv = *(const float4*)(vp + lane * 4);
        float sc = qv.x * kv.x + qv.y * kv.y + qv.z * kv.z + qv.w * kv.w;
#pragma unroll
        for (int o = 16; o; o >>= 1) sc += __shfl_xor_sync(0xffffffffu, sc, o);
        sc *= scale;
        float mn   = fmaxf(m, sc);
        float corr = expf(m - mn);
        float pw   = expf(sc - mn);
        l = l * corr + pw;
        acc.x = fmaf(pw, vv.x, acc.x * corr);
        acc.y = fmaf(pw, vv.y, acc.y * corr);
        acc.z = fmaf(pw, vv.z, acc.z * corr);
        acc.w = fmaf(pw, vv.w, acc.w * corr);
        m = mn;
    }

    __shared__ float sm_m[8], sm_l[8];
    __shared__ float sm_acc[8][HDIM];
    if (lane == 0) { sm_m[w] = m; sm_l[w] = l; }
    ((float4*)sm_acc[w])[lane] = acc;
    __syncthreads();

    if (tid < HDIM) {
        const int d = tid;
        float M = -1e30f;
#pragma unroll
        for (int i = 0; i < 8; i++) M = fmaxf(M, sm_m[i]);
        float L = 0.f, O = 0.f;
#pragma unroll
        for (int i = 0; i < 8; i++) {
            float e = expf(sm_m[i] - M);
            L += sm_l[i] * e;
            O += sm_acc[i][d] * e;
        }
        const int bh = b * HH + hh;
        if (d == 0) {
            g_pt[0][slab * 2048 + bh]        = M;
            g_pt[0][8192 + slab * 2048 + bh] = L;
        }
        g_pt[4 + slab][(size_t)bh * HDIM + d] = O;
    }
}

// ---------------- flash-decode attention: slab reduce -> att bf16 hi/lo ----
__global__ __launch_bounds__(128) void attn_reduce_kernel(const int* __restrict__ clens)
{
    const int hh = blockIdx.x, b = blockIdx.y, d = threadIdx.x;
    const int ctx = clens[b];
    const int ns = (ctx + 127) >> 7;
    const int bh = b * HH + hh;

    float M = -1e30f;
    for (int s = 0; s < ns; s++) M = fmaxf(M, g_pt[0][s * 2048 + bh]);
    float L = 0.f, O = 0.f;
    for (int s = 0; s < ns; s++) {
        float e = expf(g_pt[0][s * 2048 + bh] - M);
        L += g_pt[0][8192 + s * 2048 + bh] * e;
        O += g_pt[4 + s][(size_t)bh * HDIM + d] * e;
    }
    float o = O / L;
    __nv_bfloat16 hi = __float2bfloat16_rn(o);
    __nv_bfloat16 lo = __float2bfloat16_rn(o - __bfloat162float(hi));
    g_ath[(size_t)b * DD + hh * HDIM + d] = hi;
    g_atl[(size_t)b * DD + hh * HDIM + d] = lo;
}

// ---------------- x2 = sum(pt)+resid ; h2 = rmsnorm(x2)*g -> bf16 hi/lo ----
__global__ __launch_bounds__(256) void addreduce_rms_kernel(
    const float* __restrict__ resid, const float* __restrict__ g,
    float* __restrict__ xout)
{
    int row = blockIdx.x, tid = threadIdx.x;
    const float4* r4 = (const float4*)(resid + (size_t)row * DD);
    const float4* gr = (const float4*)g;
    float4 v[4];
    float ss = 0.f;
#pragma unroll
    for (int i = 0; i < 4; i++) {
        int idx = tid + 256 * i;
        float4 s = r4[idx];
#pragma unroll
        for (int j = 0; j < 16; j++) {
            float4 t = ((const float4*)(g_pt[j] + (size_t)row * DD))[idx];
            s.x += t.x; s.y += t.y; s.z += t.z; s.w += t.w;
        }
        v[i] = s;
        ss += s.x * s.x + s.y * s.y + s.z * s.z + s.w * s.w;
    }
#pragma unroll
    for (int o = 16; o; o >>= 1) ss += __shfl_xor_sync(0xffffffffu, ss, o);
    __shared__ float sred[8];
    if ((tid & 31) == 0) sred[tid >> 5] = ss;
    __syncthreads();
    float tot = 0.f;
#pragma unroll
    for (int i = 0; i < 8; i++) tot += sred[i];
    float inv = rsqrtf(tot / (float)DD + 1e-5f);
    float4* xo = (float4*)(xout + (size_t)row * DD);
#pragma unroll
    for (int i = 0; i < 4; i++) {
        int idx = tid + 256 * i;
        xo[idx] = v[i];
        float4 gv = gr[idx];
        float4 o4;
        o4.x = v[i].x * inv * gv.x;
        o4.y = v[i].y * inv * gv.y;
        o4.z = v[i].z * inv * gv.z;
        o4.w = v[i].w * inv * gv.w;
        uint2 uh, ul;
        cvt_split4(o4, uh, ul);
        *(uint2*)(g_h2h + (size_t)row * DD + idx * 4) = uh;
        *(uint2*)(g_h2l + (size_t)row * DD + idx * 4) = ul;
    }
}

// ---------------- gate = silu(ff1a+ff1b)*(ff3a+ff3b) -> bf16 hi/lo ---------
__global__ __launch_bounds__(256) void silu_mul_kernel()
{
    int idx = blockIdx.x * 256 + threadIdx.x;
    float4 a  = ((const float4*)g_ff1)[idx];
    float4 ab = ((const float4*)g_ff1b)[idx];
    float4 c  = ((const float4*)g_ff3)[idx];
    float4 cb = ((const float4*)g_ff3b)[idx];
    a.x += ab.x; a.y += ab.y; a.z += ab.z; a.w += ab.w;
    c.x += cb.x; c.y += cb.y; c.z += cb.z; c.w += cb.w;
    float4 o;
    o.x = a.x / (1.f + __expf(-a.x)) * c.x;
    o.y = a.y / (1.f + __expf(-a.y)) * c.y;
    o.z = a.z / (1.f + __expf(-a.z)) * c.z;
    o.w = a.w / (1.f + __expf(-a.w)) * c.w;
    uint2 uh, ul;
    cvt_split4(o, uh, ul);
    *(uint2*)(g_gh + (size_t)idx * 4) = uh;
    *(uint2*)(g_gl + (size_t)idx * 4) = ul;
}

// ---------------- out = sum(pt) + resid ----------------
__global__ __launch_bounds__(256) void final_add_kernel(
    const float* __restrict__ resid, float* __restrict__ out)
{
    int idx = blockIdx.x * 256 + threadIdx.x;
    float4 s = ((const float4*)resid)[idx];
#pragma unroll
    for (int j = 0; j < 16; j++) {
        float4 t = ((const float4*)g_pt[j])[idx];
        s.x += t.x; s.y += t.y; s.z += t.z; s.w += t.w;
    }
    ((float4*)out)[idx] = s;
}

// ---------------- host driver ----------------
extern "C" void kernel_launch(void* const* d_in, const int* in_sizes, int n_in,
                              void* d_out, int out_size)
{
    const float* x     = (const float*)d_in[0];
    const float* kheap = (const float*)d_in[1];
    const float* vheap = (const float*)d_in[2];
    const int*   btab  = (const int*)d_in[3];
    const int*   clens = (const int*)d_in[5];
    const float* scale = (const float*)d_in[9];
    const float* Wq    = (const float*)d_in[13];
    const float* Wk    = (const float*)d_in[14];
    const float* Wv    = (const float*)d_in[15];
    const float* Wo    = (const float*)d_in[16];
    const float* W1    = (const float*)d_in[17];
    const float* W2    = (const float*)d_in[18];
    const float* W3    = (const float*)d_in[19];
    const float* g1    = (const float*)d_in[20];
    const float* g2    = (const float*)d_in[21];
    float* out = (float*)d_out;

    float *x2, *ff1, *ff1b, *ff3, *ff3b;
    __nv_bfloat16 *hh, *hl, *ath, *atl, *h2h, *h2l, *gh, *gl;
    float* pt[16];
    cudaGetSymbolAddress((void**)&x2,   g_x2);
    cudaGetSymbolAddress((void**)&ff1,  g_ff1);
    cudaGetSymbolAddress((void**)&ff1b, g_ff1b);
    cudaGetSymbolAddress((void**)&ff3,  g_ff3);
    cudaGetSymbolAddress((void**)&ff3b, g_ff3b);
    cudaGetSymbolAddress((void**)&hh,   g_hh);
    cudaGetSymbolAddress((void**)&hl,   g_hl);
    cudaGetSymbolAddress((void**)&ath,  g_ath);
    cudaGetSymbolAddress((void**)&atl,  g_atl);
    cudaGetSymbolAddress((void**)&h2h,  g_h2h);
    cudaGetSymbolAddress((void**)&h2l,  g_h2l);
    cudaGetSymbolAddress((void**)&gh,   g_gh);
    cudaGetSymbolAddress((void**)&gl,   g_gl);
    {
        float* base;
        cudaGetSymbolAddress((void**)&base, g_pt);
        for (int j = 0; j < 16; j++) pt[j] = base + (size_t)j * BB * DD;
    }

    const int SMEM = 2 * STAGE_BYTES;
    cudaFuncSetAttribute(bf16gemm_kernel,
                         cudaFuncAttributeMaxDynamicSharedMemorySize, SMEM);

    // 1) h = rmsnorm(x)*g1 -> bf16 hi/lo
    rmsnorm_kernel<<<BB, 256>>>(x, g1, hh, hl);

    // 2) q,k,v = h @ {Wq,Wk,Wv}^T   split-K=4 each -> 384 CTAs
    {
        GP p;
        p.Ah = hh; p.Al = hl; p.lda = DD; p.ldc = DD; p.nbpj = DD / 128;
        const float* Ws[3] = {Wq, Wk, Wv};
        for (int m = 0; m < 3; m++)
            for (int s = 0; s < 4; s++)
                p.jobs[m * 4 + s] = {Ws[m], pt[m * 4 + s], s * (DD / 4), (s + 1) * (DD / 4)};
        bf16gemm_kernel<<<12 * (DD / 128), 256, SMEM>>>(p);
    }
    qkv_combine_kernel<<<(BB * DD) / 4 / 256, 256>>>();

    // 3) flash-decode attention
    attn_partial_kernel<<<dim3(HH, BB, NSLAB), 256>>>(kheap, vheap, btab, clens, scale);
    attn_reduce_kernel<<<dim3(HH, BB), 128>>>(clens);

    // 4) att @ Wo^T, split-K=16 -> 512 CTAs
    {
        GP p;
        p.Ah = ath; p.Al = atl; p.lda = DD; p.ldc = DD; p.nbpj = DD / 128;
        for (int s = 0; s < 16; s++)
            p.jobs[s] = {Wo, pt[s], s * (DD / 16), (s + 1) * (DD / 16)};
        bf16gemm_kernel<<<16 * (DD / 128), 256, SMEM>>>(p);
    }

    // 5) x2 = sum(pt)+x ; h2 -> bf16 hi/lo
    addreduce_rms_kernel<<<BB, 256>>>(x, g2, x2);

    // 6) ff1 = h2 @ W1^T, ff3 = h2 @ W3^T, split-K=2 each -> 512 CTAs
    {
        GP p;
        p.Ah = h2h; p.Al = h2l; p.lda = DD; p.ldc = DFF; p.nbpj = DFF / 128;
        p.jobs[0] = {W1, ff1,  0,      DD / 2};
        p.jobs[1] = {W1, ff1b, DD / 2, DD};
        p.jobs[2] = {W3, ff3,  0,      DD / 2};
        p.jobs[3] = {W3, ff3b, DD / 2, DD};
        bf16gemm_kernel<<<4 * (DFF / 128), 256, SMEM>>>(p);
    }

    // 7) gate -> bf16 hi/lo
    silu_mul_kernel<<<(BB * DFF) / 4 / 256, 256>>>();

    // 8) gate @ W2^T, split-K=16 -> 512 CTAs
    {
        GP p;
        p.Ah = gh; p.Al = gl; p.lda = DFF; p.ldc = DD; p.nbpj = DD / 128;
        for (int s = 0; s < 16; s++)
            p.jobs[s] = {W2, pt[s], s * (DFF / 16), (s + 1) * (DFF / 16)};
        bf16gemm_kernel<<<16 * (DD / 128), 256, SMEM>>>(p);
    }

    // 9) out = sum(pt) + x2
    final_add_kernel<<<(BB * DD) / 4 / 256, 256>>>(x2, out);
}

// round 16
// speedup vs baseline: 1.4913x; 1.0422x over previous
#include <cuda_runtime.h>
#include <cuda_bf16.h>
#include <math.h>
#include <stdint.h>

#define BB   64
#define DD   4096
#define HH   32
#define HDIM 128
#define PBS  16
#define MBSN 32
#define DFF  16384
#define NSLAB 4

// ---------------- device scratch ----------------
__device__ float g_q  [BB * DD];
__device__ float g_k  [BB * DD];
__device__ float g_v  [BB * DD];
__device__ float g_x2 [BB * DD];
__device__ float g_pt [16][BB * DD];     // split-K partials / attention partials
__device__ float g_ff1 [BB * DFF];
__device__ float g_ff3 [BB * DFF];
// pre-split bf16 activations (hi/lo)
__device__ __nv_bfloat16 g_hh [BB * DD],  g_hl [BB * DD];
__device__ __nv_bfloat16 g_ath[BB * DD],  g_atl[BB * DD];
__device__ __nv_bfloat16 g_h2h[BB * DD],  g_h2l[BB * DD];
__device__ __nv_bfloat16 g_gh [BB * DFF], g_gl [BB * DFF];

// ---------------- PTX helpers ----------------
#define LDSM4(r0, r1, r2, r3, addr)                                          \
    asm volatile("ldmatrix.sync.aligned.m8n8.x4.shared.b16 {%0,%1,%2,%3}, [%4];" \
                 : "=r"(r0), "=r"(r1), "=r"(r2), "=r"(r3) : "r"(addr))

#define MMA16816(d, a0, a1, a2, a3, b0, b1)                                   \
    asm volatile("mma.sync.aligned.m16n8k16.row.col.f32.bf16.bf16.f32 "       \
                 "{%0,%1,%2,%3},{%4,%5,%6,%7},{%8,%9},{%0,%1,%2,%3};"         \
                 : "+f"(d[0]), "+f"(d[1]), "+f"(d[2]), "+f"(d[3])             \
                 : "r"(a0), "r"(a1), "r"(a2), "r"(a3), "r"(b0), "r"(b1))

// split fp32 -> (hi, lo) bf16, packed pairs
__device__ __forceinline__ void cvt_split4(float4 v, uint2& uh, uint2& ul)
{
    __nv_bfloat162 h01 = __floats2bfloat162_rn(v.x, v.y);
    __nv_bfloat162 h23 = __floats2bfloat162_rn(v.z, v.w);
    float lx = v.x - __bfloat162float(__low2bfloat16(h01));
    float ly = v.y - __bfloat162float(__high2bfloat16(h01));
    float lz = v.z - __bfloat162float(__low2bfloat16(h23));
    float lw = v.w - __bfloat162float(__high2bfloat16(h23));
    __nv_bfloat162 l01 = __floats2bfloat162_rn(lx, ly);
    __nv_bfloat162 l23 = __floats2bfloat162_rn(lz, lw);
    uh.x = *(unsigned int*)&h01; uh.y = *(unsigned int*)&h23;
    ul.x = *(unsigned int*)&l01; ul.y = *(unsigned int*)&l23;
}

// ---------------- bf16-split tensor-core GEMM (2-stage pipelined) --------
// A pre-split (bf16 hi/lo). Loaders lane-consecutive (minimal L1tex wavefronts).
struct Job { const float* W; float* C; int k0, k1; };
struct GP  {
    const __nv_bfloat16* Ah;
    const __nv_bfloat16* Al;
    int lda; int ldc; int nbpj; Job jobs[16];
};

#define KPAD 72
#define ST_ELE (2 * 64 * KPAD + 2 * 128 * KPAD)
#define STAGE_BYTES (ST_ELE * 2)

__global__ __launch_bounds__(256, 2) void bf16gemm_kernel(GP p)
{
    int job = blockIdx.x / p.nbpj;
    int nb  = blockIdx.x % p.nbpj;
    const float* W = p.jobs[job].W;
    float*       C = p.jobs[job].C;
    const int k0j = p.jobs[job].k0, k1j = p.jobs[job].k1;
    const int n0  = nb * 128;

    extern __shared__ __nv_bfloat16 smem_bf[];

    const int tid = threadIdx.x, lane = tid & 31, w = tid >> 5;
    const int wm = w & 1, wn = w >> 1;

    const int arow = (lane & 7) + (lane & 8);
    const int acol = (lane & 16) >> 1;
    const int brow = (lane & 7) + ((lane & 16) >> 1);
    const int bcol = lane & 8;

    float acc[2][4][4];
#pragma unroll
    for (int i = 0; i < 2; i++)
#pragma unroll
        for (int j = 0; j < 4; j++)
#pragma unroll
            for (int t = 0; t < 4; t++) acc[i][j][t] = 0.f;

    // ---- A loader: warp covers 8 rows; each instr = 4 full rows ----
    const int aRow = (w << 3) + (lane >> 3);
    const int aCol = (lane & 7) * 8;
    const __nv_bfloat16* Ahp = p.Ah + (size_t)aRow * p.lda + k0j + aCol;
    const __nv_bfloat16* Alp = p.Al + (size_t)aRow * p.lda + k0j + aCol;
    const size_t aStep = (size_t)4 * p.lda;
    __nv_bfloat16* saH = smem_bf + aRow * KPAD + aCol;

    // ---- W loader: warp covers 16 rows; each instr = 2 full rows ----
    const int wRow = (w << 4) + (lane >> 4);
    const int wCol = (lane & 15) * 4;
    const float* Wp = W + (size_t)(n0 + wRow) * p.lda + k0j + wCol;
    const size_t wStep = (size_t)2 * p.lda;
    __nv_bfloat16* sbH = smem_bf + 2 * 64 * KPAD + wRow * KPAD + wCol;

    unsigned int a_base[2], b_base[2];
#pragma unroll
    for (int mi = 0; mi < 2; mi++)
        a_base[mi] = (unsigned int)__cvta_generic_to_shared(
            smem_bf + (wm * 32 + mi * 16 + arow) * KPAD + acol);
#pragma unroll
    for (int nj = 0; nj < 2; nj++)
        b_base[nj] = (unsigned int)__cvta_generic_to_shared(
            smem_bf + 2 * 64 * KPAD + (wn * 32 + nj * 16 + brow) * KPAD + bcol);
    const unsigned int A_LO = 64 * KPAD * 2;    // bytes
    const unsigned int B_LO = 128 * KPAD * 2;
    const int A_LOe = 64 * KPAD;                // elems
    const int B_LOe = 128 * KPAD;

    const int nch = (k1j - k0j) >> 6;

    uint4 rah[2], ral[2];
    float4 rw[8];
    rah[0] = *(const uint4*)(Ahp);          rah[1] = *(const uint4*)(Ahp + aStep);
    ral[0] = *(const uint4*)(Alp);          ral[1] = *(const uint4*)(Alp + aStep);
#pragma unroll
    for (int i = 0; i < 8; i++) rw[i] = *(const float4*)(Wp + (size_t)i * wStep);

    *(uint4*)(saH)                 = rah[0];
    *(uint4*)(saH + 4 * KPAD)      = rah[1];
    *(uint4*)(saH + A_LOe)             = ral[0];
    *(uint4*)(saH + A_LOe + 4 * KPAD)  = ral[1];
#pragma unroll
    for (int i = 0; i < 8; i++) {
        uint2 uh, ul;
        cvt_split4(rw[i], uh, ul);
        *(uint2*)(sbH + i * 2 * KPAD)          = uh;
        *(uint2*)(sbH + B_LOe + i * 2 * KPAD)  = ul;
    }
    __syncthreads();

    for (int c = 0; c < nch; c++) {
        const bool more = (c + 1) < nch;
        if (more) {
            const int kn = (c + 1) * 64;
            rah[0] = *(const uint4*)(Ahp + kn);          rah[1] = *(const uint4*)(Ahp + kn + aStep);
            ral[0] = *(const uint4*)(Alp + kn);          ral[1] = *(const uint4*)(Alp + kn + aStep);
#pragma unroll
            for (int i = 0; i < 8; i++) rw[i] = *(const float4*)(Wp + kn + (size_t)i * wStep);
        }

        const unsigned int sb_off = (unsigned int)(c & 1) * STAGE_BYTES;
#pragma unroll
        for (int ks = 0; ks < 4; ks++) {
            const unsigned int koff = sb_off + ks * 16 * 2;
            unsigned int ah[2][4], al[2][4], bh[2][4], bl[2][4];
#pragma unroll
            for (int mi = 0; mi < 2; mi++) {
                LDSM4(ah[mi][0], ah[mi][1], ah[mi][2], ah[mi][3], a_base[mi] + koff);
                LDSM4(al[mi][0], al[mi][1], al[mi][2], al[mi][3], a_base[mi] + koff + A_LO);
            }
#pragma unroll
            for (int nj = 0; nj < 2; nj++) {
                LDSM4(bh[nj][0], bh[nj][1], bh[nj][2], bh[nj][3], b_base[nj] + koff);
                LDSM4(bl[nj][0], bl[nj][1], bl[nj][2], bl[nj][3], b_base[nj] + koff + B_LO);
            }
#pragma unroll
            for (int mi = 0; mi < 2; mi++)
#pragma unroll
                for (int ni = 0; ni < 4; ni++) {
                    const int nj = ni >> 1, of = (ni & 1) * 2;
                    MMA16816(acc[mi][ni], ah[mi][0], ah[mi][1], ah[mi][2], ah[mi][3],
                             bh[nj][of], bh[nj][of + 1]);
                    MMA16816(acc[mi][ni], ah[mi][0], ah[mi][1], ah[mi][2], ah[mi][3],
                             bl[nj][of], bl[nj][of + 1]);
                    MMA16816(acc[mi][ni], al[mi][0], al[mi][1], al[mi][2], al[mi][3],
                             bh[nj][of], bh[nj][of + 1]);
                }
        }

        if (more) {
            const int st = ((c + 1) & 1) * ST_ELE;
            *(uint4*)(saH + st)                 = rah[0];
            *(uint4*)(saH + st + 4 * KPAD)      = rah[1];
            *(uint4*)(saH + st + A_LOe)             = ral[0];
            *(uint4*)(saH + st + A_LOe + 4 * KPAD)  = ral[1];
#pragma unroll
            for (int i = 0; i < 8; i++) {
                uint2 uh, ul;
                cvt_split4(rw[i], uh, ul);
                *(uint2*)(sbH + st + i * 2 * KPAD)          = uh;
                *(uint2*)(sbH + st + B_LOe + i * 2 * KPAD)  = ul;
            }
        }
        __syncthreads();
    }

    const int tr = lane >> 2, tc = (lane & 3) * 2;
#pragma unroll
    for (int mi = 0; mi < 2; mi++) {
        const int m = wm * 32 + mi * 16 + tr;
#pragma unroll
        for (int ni = 0; ni < 4; ni++) {
            const int n = n0 + wn * 32 + ni * 8 + tc;
            float2 r0 = {acc[mi][ni][0], acc[mi][ni][1]};
            float2 r1 = {acc[mi][ni][2], acc[mi][ni][3]};
            *(float2*)&C[(size_t)m * p.ldc + n]       = r0;
            *(float2*)&C[(size_t)(m + 8) * p.ldc + n] = r1;
        }
    }
}

// ---------------- RMSNorm -> bf16 hi/lo ----------------
__global__ __launch_bounds__(256) void rmsnorm_kernel(
    const float* __restrict__ x, const float* __restrict__ g,
    __nv_bfloat16* __restrict__ oh, __nv_bfloat16* __restrict__ ol)
{
    int row = blockIdx.x, tid = threadIdx.x;
    const float4* xr = (const float4*)(x + (size_t)row * DD);
    const float4* gr = (const float4*)g;
    float4 v[4];
    float ss = 0.f;
#pragma unroll
    for (int i = 0; i < 4; i++) {
        v[i] = xr[tid + 256 * i];
        ss += v[i].x * v[i].x + v[i].y * v[i].y + v[i].z * v[i].z + v[i].w * v[i].w;
    }
#pragma unroll
    for (int o = 16; o; o >>= 1) ss += __shfl_xor_sync(0xffffffffu, ss, o);
    __shared__ float sred[8];
    if ((tid & 31) == 0) sred[tid >> 5] = ss;
    __syncthreads();
    float tot = 0.f;
#pragma unroll
    for (int i = 0; i < 8; i++) tot += sred[i];
    float inv = rsqrtf(tot / (float)DD + 1e-5f);
#pragma unroll
    for (int i = 0; i < 4; i++) {
        int idx = tid + 256 * i;
        float4 gv = gr[idx];
        float4 o4;
        o4.x = v[i].x * inv * gv.x;
        o4.y = v[i].y * inv * gv.y;
        o4.z = v[i].z * inv * gv.z;
        o4.w = v[i].w * inv * gv.w;
        uint2 uh, ul;
        cvt_split4(o4, uh, ul);
        *(uint2*)(oh + (size_t)row * DD + idx * 4) = uh;
        *(uint2*)(ol + (size_t)row * DD + idx * 4) = ul;
    }
}

// ---------------- combine QKV split-K partials (3 per matrix) ----------------
__global__ __launch_bounds__(256) void qkv_combine_kernel()
{
    int idx = blockIdx.x * 256 + threadIdx.x;
#pragma unroll
    for (int m = 0; m < 3; m++) {
        float4 s = ((const float4*)g_pt[m * 3 + 0])[idx];
#pragma unroll
        for (int j = 1; j < 3; j++) {
            float4 t = ((const float4*)g_pt[m * 3 + j])[idx];
            s.x += t.x; s.y += t.y; s.z += t.z; s.w += t.w;
        }
        float* dst = (m == 0) ? g_q : (m == 1) ? g_k : g_v;
        ((float4*)dst)[idx] = s;
    }
}

// ---------------- flash-decode attention: slab partial (R10 variant) ------
__global__ __launch_bounds__(256) void attn_partial_kernel(
    const float* __restrict__ kheap, const float* __restrict__ vheap,
    const int*   __restrict__ btab,  const int*  __restrict__ clens,
    const float* __restrict__ scale_p)
{
    const int hh = blockIdx.x, b = blockIdx.y, slab = blockIdx.z;
    const int ctx = clens[b];
    const int base = slab * 128;
    if (base >= ctx) return;
    const int send = min(ctx, base + 128);

    const int tid = threadIdx.x, lane = tid & 31, w = tid >> 5;
    const float scale = scale_p[0];
    const int last = ctx - 1;

    const float4 qv = ((const float4*)(g_q + (size_t)b * DD + hh * HDIM))[lane];

    float m = -1e30f, l = 0.f;
    float4 acc = {0.f, 0.f, 0.f, 0.f};

    for (int s = base + w; s < send; s += 8) {
        const float *kp, *vp;
        if (s == last) {
            kp = g_k + (size_t)b * DD + hh * HDIM;
            vp = g_v + (size_t)b * DD + hh * HDIM;
        } else {
            int blk = btab[b * MBSN + (s >> 4)];
            size_t hbase = (((size_t)blk * HH + hh) * PBS + (s & 15)) * HDIM;
            kp = kheap + hbase;
            vp = vheap + hbase;
        }
        float4 kv = *(const float4*)(kp + lane * 4);
        float4 vv = *(const float4*)(vp + lane * 4);
        float sc = qv.x * kv.x + qv.y * kv.y + qv.z * kv.z + qv.w * kv.w;
#pragma unroll
        for (int o = 16; o; o >>= 1) sc += __shfl_xor_sync(0xffffffffu, sc, o);
        sc *= scale;
        float mn   = fmaxf(m, sc);
        float corr = expf(m - mn);
        float pw   = expf(sc - mn);
        l = l * corr + pw;
        acc.x = fmaf(pw, vv.x, acc.x * corr);
        acc.y = fmaf(pw, vv.y, acc.y * corr);
        acc.z = fmaf(pw, vv.z, acc.z * corr);
        acc.w = fmaf(pw, vv.w, acc.w * corr);
        m = mn;
    }

    __shared__ float sm_m[8], sm_l[8];
    __shared__ float sm_acc[8][HDIM];
    if (lane == 0) { sm_m[w] = m; sm_l[w] = l; }
    ((float4*)sm_acc[w])[lane] = acc;
    __syncthreads();

    if (tid < HDIM) {
        const int d = tid;
        float M = -1e30f;
#pragma unroll
        for (int i = 0; i < 8; i++) M = fmaxf(M, sm_m[i]);
        float L = 0.f, O = 0.f;
#pragma unroll
        for (int i = 0; i < 8; i++) {
            float e = expf(sm_m[i] - M);
            L += sm_l[i] * e;
            O += sm_acc[i][d] * e;
        }
        const int bh = b * HH + hh;
        if (d == 0) {
            g_pt[0][slab * 2048 + bh]        = M;
            g_pt[0][8192 + slab * 2048 + bh] = L;
        }
        g_pt[4 + slab][(size_t)bh * HDIM + d] = O;
    }
}

// ---------------- flash-decode attention: slab reduce -> att bf16 hi/lo ----
__global__ __launch_bounds__(128) void attn_reduce_kernel(const int* __restrict__ clens)
{
    const int hh = blockIdx.x, b = blockIdx.y, d = threadIdx.x;
    const int ctx = clens[b];
    const int ns = (ctx + 127) >> 7;
    const int bh = b * HH + hh;

    float M = -1e30f;
    for (int s = 0; s < ns; s++) M = fmaxf(M, g_pt[0][s * 2048 + bh]);
    float L = 0.f, O = 0.f;
    for (int s = 0; s < ns; s++) {
        float e = expf(g_pt[0][s * 2048 + bh] - M);
        L += g_pt[0][8192 + s * 2048 + bh] * e;
        O += g_pt[4 + s][(size_t)bh * HDIM + d] * e;
    }
    float o = O / L;
    __nv_bfloat16 hi = __float2bfloat16_rn(o);
    __nv_bfloat16 lo = __float2bfloat16_rn(o - __bfloat162float(hi));
    g_ath[(size_t)b * DD + hh * HDIM + d] = hi;
    g_atl[(size_t)b * DD + hh * HDIM + d] = lo;
}

// ---------------- x2 = sum(pt[0..8])+resid ; h2 -> bf16 hi/lo ----
__global__ __launch_bounds__(256) void addreduce_rms_kernel(
    const float* __restrict__ resid, const float* __restrict__ g,
    float* __restrict__ xout)
{
    int row = blockIdx.x, tid = threadIdx.x;
    const float4* r4 = (const float4*)(resid + (size_t)row * DD);
    const float4* gr = (const float4*)g;
    float4 v[4];
    float ss = 0.f;
#pragma unroll
    for (int i = 0; i < 4; i++) {
        int idx = tid + 256 * i;
        float4 s = r4[idx];
#pragma unroll
        for (int j = 0; j < 9; j++) {
            float4 t = ((const float4*)(g_pt[j] + (size_t)row * DD))[idx];
            s.x += t.x; s.y += t.y; s.z += t.z; s.w += t.w;
        }
        v[i] = s;
        ss += s.x * s.x + s.y * s.y + s.z * s.z + s.w * s.w;
    }
#pragma unroll
    for (int o = 16; o; o >>= 1) ss += __shfl_xor_sync(0xffffffffu, ss, o);
    __shared__ float sred[8];
    if ((tid & 31) == 0) sred[tid >> 5] = ss;
    __syncthreads();
    float tot = 0.f;
#pragma unroll
    for (int i = 0; i < 8; i++) tot += sred[i];
    float inv = rsqrtf(tot / (float)DD + 1e-5f);
    float4* xo = (float4*)(xout + (size_t)row * DD);
#pragma unroll
    for (int i = 0; i < 4; i++) {
        int idx = tid + 256 * i;
        xo[idx] = v[i];
        float4 gv = gr[idx];
        float4 o4;
        o4.x = v[i].x * inv * gv.x;
        o4.y = v[i].y * inv * gv.y;
        o4.z = v[i].z * inv * gv.z;
        o4.w = v[i].w * inv * gv.w;
        uint2 uh, ul;
        cvt_split4(o4, uh, ul);
        *(uint2*)(g_h2h + (size_t)row * DD + idx * 4) = uh;
        *(uint2*)(g_h2l + (size_t)row * DD + idx * 4) = ul;
    }
}

// ---------------- gate = silu(ff1)*ff3 -> bf16 hi/lo ---------
__global__ __launch_bounds__(256) void silu_mul_kernel()
{
    int idx = blockIdx.x * 256 + threadIdx.x;
    float4 a = ((const float4*)g_ff1)[idx];
    float4 c = ((const float4*)g_ff3)[idx];
    float4 o;
    o.x = a.x / (1.f + __expf(-a.x)) * c.x;
    o.y = a.y / (1.f + __expf(-a.y)) * c.y;
    o.z = a.z / (1.f + __expf(-a.z)) * c.z;
    o.w = a.w / (1.f + __expf(-a.w)) * c.w;
    uint2 uh, ul;
    cvt_split4(o, uh, ul);
    *(uint2*)(g_gh + (size_t)idx * 4) = uh;
    *(uint2*)(g_gl + (size_t)idx * 4) = ul;
}

// ---------------- out = sum(pt[0..7]) + resid ----------------
__global__ __launch_bounds__(256) void final_add_kernel(
    const float* __restrict__ resid, float* __restrict__ out)
{
    int idx = blockIdx.x * 256 + threadIdx.x;
    float4 s = ((const float4*)resid)[idx];
#pragma unroll
    for (int j = 0; j < 8; j++) {
        float4 t = ((const float4*)g_pt[j])[idx];
        s.x += t.x; s.y += t.y; s.z += t.z; s.w += t.w;
    }
    ((float4*)out)[idx] = s;
}

// ---------------- host driver ----------------
extern "C" void kernel_launch(void* const* d_in, const int* in_sizes, int n_in,
                              void* d_out, int out_size)
{
    const float* x     = (const float*)d_in[0];
    const float* kheap = (const float*)d_in[1];
    const float* vheap = (const float*)d_in[2];
    const int*   btab  = (const int*)d_in[3];
    const int*   clens = (const int*)d_in[5];
    const float* scale = (const float*)d_in[9];
    const float* Wq    = (const float*)d_in[13];
    const float* Wk    = (const float*)d_in[14];
    const float* Wv    = (const float*)d_in[15];
    const float* Wo    = (const float*)d_in[16];
    const float* W1    = (const float*)d_in[17];
    const float* W2    = (const float*)d_in[18];
    const float* W3    = (const float*)d_in[19];
    const float* g1    = (const float*)d_in[20];
    const float* g2    = (const float*)d_in[21];
    float* out = (float*)d_out;

    float *x2, *ff1, *ff3;
    __nv_bfloat16 *hh, *hl, *ath, *atl, *h2h, *h2l, *gh, *gl;
    float* pt[16];
    cudaGetSymbolAddress((void**)&x2,   g_x2);
    cudaGetSymbolAddress((void**)&ff1,  g_ff1);
    cudaGetSymbolAddress((void**)&ff3,  g_ff3);
    cudaGetSymbolAddress((void**)&hh,   g_hh);
    cudaGetSymbolAddress((void**)&hl,   g_hl);
    cudaGetSymbolAddress((void**)&ath,  g_ath);
    cudaGetSymbolAddress((void**)&atl,  g_atl);
    cudaGetSymbolAddress((void**)&h2h,  g_h2h);
    cudaGetSymbolAddress((void**)&h2l,  g_h2l);
    cudaGetSymbolAddress((void**)&gh,   g_gh);
    cudaGetSymbolAddress((void**)&gl,   g_gl);
    {
        float* base;
        cudaGetSymbolAddress((void**)&base, g_pt);
        for (int j = 0; j < 16; j++) pt[j] = base + (size_t)j * BB * DD;
    }

    const int SMEM = 2 * STAGE_BYTES;
    cudaFuncSetAttribute(bf16gemm_kernel,
                         cudaFuncAttributeMaxDynamicSharedMemorySize, SMEM);

    // 1) h = rmsnorm(x)*g1 -> bf16 hi/lo
    rmsnorm_kernel<<<BB, 256>>>(x, g1, hh, hl);

    // 2) q,k,v: split-K=3 each -> 9 jobs x 32 = 288 CTAs (one wave)
    {
        static const int kb[4] = {0, 1408, 2752, 4096};  // 22/21/21 chunks
        GP p;
        p.Ah = hh; p.Al = hl; p.lda = DD; p.ldc = DD; p.nbpj = DD / 128;
        const float* Ws[3] = {Wq, Wk, Wv};
        for (int m = 0; m < 3; m++)
            for (int s = 0; s < 3; s++)
                p.jobs[m * 3 + s] = {Ws[m], pt[m * 3 + s], kb[s], kb[s + 1]};
        bf16gemm_kernel<<<9 * (DD / 128), 256, SMEM>>>(p);
    }
    qkv_combine_kernel<<<(BB * DD) / 4 / 256, 256>>>();

    // 3) flash-decode attention
    attn_partial_kernel<<<dim3(HH, BB, NSLAB), 256>>>(kheap, vheap, btab, clens, scale);
    attn_reduce_kernel<<<dim3(HH, BB), 128>>>(clens);

    // 4) att @ Wo^T, split-K=9 (8,7x8 chunks) -> 288 CTAs (one wave)
    {
        static const int kb[10] = {0, 512, 960, 1408, 1856, 2304, 2752, 3200, 3648, 4096};
        GP p;
        p.Ah = ath; p.Al = atl; p.lda = DD; p.ldc = DD; p.nbpj = DD / 128;
        for (int s = 0; s < 9; s++)
            p.jobs[s] = {Wo, pt[s], kb[s], kb[s + 1]};
        bf16gemm_kernel<<<9 * (DD / 128), 256, SMEM>>>(p);
    }

    // 5) x2 = sum(pt[0..8])+x ; h2 -> bf16 hi/lo
    addreduce_rms_kernel<<<BB, 256>>>(x, g2, x2);

    // 6) ff1 = h2 @ W1^T, ff3 = h2 @ W3^T, split-K=1 -> 256 CTAs (one wave)
    {
        GP p;
        p.Ah = h2h; p.Al = h2l; p.lda = DD; p.ldc = DFF; p.nbpj = DFF / 128;
        p.jobs[0] = {W1, ff1, 0, DD};
        p.jobs[1] = {W3, ff3, 0, DD};
        bf16gemm_kernel<<<2 * (DFF / 128), 256, SMEM>>>(p);
    }

    // 7) gate -> bf16 hi/lo
    silu_mul_kernel<<<(BB * DFF) / 4 / 256, 256>>>();

    // 8) gate @ W2^T, split-K=8 -> 256 CTAs (one wave)
    {
        GP p;
        p.Ah = gh; p.Al = gl; p.lda = DFF; p.ldc = DD; p.nbpj = DD / 128;
        for (int s = 0; s < 8; s++)
            p.jobs[s] = {W2, pt[s], s * (DFF / 8), (s + 1) * (DFF / 8)};
        bf16gemm_kernel<<<8 * (DD / 128), 256, SMEM>>>(p);
    }

    // 9) out = sum(pt[0..7]) + x2
    final_add_kernel<<<(BB * DD) / 4 / 256, 256>>>(x2, out);
}